// round 4
// baseline (speedup 1.0000x reference)
#include <cuda_runtime.h>

#define BATCH 128
#define DG 512
#define DH 1024
#define LAM 0.95f
#define ETA 0.5f
#define LN_EPS 1e-5f

#define GANGS 6
#define GANG_BLOCKS 64          // 64 blocks/gang x 16 rows = 1024 rows
#define ROWS_PER_BLOCK 16
#define FUSED_GRID (GANGS * GANG_BLOCKS)
// dynamic smem: tile(16*1024) + s_h(1024) + s_red(32)
#define FUSED_SMEM ((ROWS_PER_BLOCK * DH + DH + 32) * sizeof(float))

// Scratch (allocation-free)
__device__ float g_base[BATCH * DH];
__device__ float g_y0[BATCH * DH];
__device__ float g_y1[BATCH * DH];
__device__ int   g_arrive[BATCH];

// ---------------------------------------------------------------------------
// Kernel 1: base = h_prev@Wh^T + z@Wg^T + bh. Also zeroes gang counters.
// ---------------------------------------------------------------------------
__global__ void base_gemm_kernel(const float* __restrict__ Hp,
                                 const float* __restrict__ Z,
                                 const float* __restrict__ Wh,
                                 const float* __restrict__ Wg,
                                 const float* __restrict__ bh)
{
    __shared__ float Hs[32][33];
    __shared__ float Ws[32][33];

    const int tid = threadIdx.x;
    if (tid == 0) {
        int lin = blockIdx.x + gridDim.x * blockIdx.y;   // 0..127
        if (lin < BATCH) g_arrive[lin] = 0;
    }

    const int tx = tid & 15;
    const int ty = tid >> 4;
    const int bm0 = blockIdx.x * 32;
    const int n0  = blockIdx.y * 32;

    float acc00 = 0.f, acc01 = 0.f, acc10 = 0.f, acc11 = 0.f;

    for (int k0 = 0; k0 < DH + DG; k0 += 32) {
        const float* src;
        const float* wsrc;
        int K, kk0;
        if (k0 < DH) { src = Hp; wsrc = Wh; K = DH; kk0 = k0; }
        else         { src = Z;  wsrc = Wg; K = DG; kk0 = k0 - DH; }

        #pragma unroll
        for (int l = 0; l < 4; l++) {
            int idx = tid + l * 256;
            int r = idx >> 5, c = idx & 31;
            Hs[r][c] = src[(bm0 + r) * K + kk0 + c];
            Ws[r][c] = wsrc[(n0 + r) * K + kk0 + c];
        }
        __syncthreads();

        #pragma unroll
        for (int kk = 0; kk < 32; kk++) {
            float h0 = Hs[ty * 2][kk];
            float h1 = Hs[ty * 2 + 1][kk];
            float w0 = Ws[tx * 2][kk];
            float w1 = Ws[tx * 2 + 1][kk];
            acc00 += h0 * w0; acc01 += h0 * w1;
            acc10 += h1 * w0; acc11 += h1 * w1;
        }
        __syncthreads();
    }

    const int r0 = bm0 + ty * 2;
    const int c0 = n0 + tx * 2;
    const float bias0 = bh[c0];
    const float bias1 = bh[c0 + 1];
    g_base[r0 * DH + c0]           = acc00 + bias0;
    g_base[r0 * DH + c0 + 1]       = acc01 + bias1;
    g_base[(r0 + 1) * DH + c0]     = acc10 + bias0;
    g_base[(r0 + 1) * DH + c0 + 1] = acc11 + bias1;
}

// ---------------------------------------------------------------------------
// In-block LN+ReLU: 256 threads, h[b] (1024 floats) into s_h. Trailing sync.
// ---------------------------------------------------------------------------
__device__ __forceinline__ void compute_h(const float* __restrict__ base_b,
                                          const float* __restrict__ y_b,
                                          const float* __restrict__ gamma,
                                          const float* __restrict__ beta,
                                          float* __restrict__ s_h,
                                          float* __restrict__ s_red,
                                          int t)
{
    const int w = t >> 5, lane = t & 31;

    float4 x = reinterpret_cast<const float4*>(base_b)[t];
    if (y_b) {
        float4 y = reinterpret_cast<const float4*>(y_b)[t];
        x.x += y.x; x.y += y.y; x.z += y.z; x.w += y.w;
    }
    float s  = (x.x + x.y) + (x.z + x.w);
    float ss = fmaf(x.x, x.x, x.y * x.y) + fmaf(x.z, x.z, x.w * x.w);

    #pragma unroll
    for (int o = 16; o > 0; o >>= 1) {
        s  += __shfl_xor_sync(0xffffffffu, s,  o);
        ss += __shfl_xor_sync(0xffffffffu, ss, o);
    }
    if (lane == 0) { s_red[w] = s; s_red[8 + w] = ss; }
    __syncthreads();
    if (t < 32) {
        float a = (lane < 8) ? s_red[lane]     : 0.f;
        float c = (lane < 8) ? s_red[8 + lane] : 0.f;
        #pragma unroll
        for (int o = 4; o > 0; o >>= 1) {
            a += __shfl_xor_sync(0xffffffffu, a, o);
            c += __shfl_xor_sync(0xffffffffu, c, o);
        }
        if (lane == 0) { s_red[0] = a; s_red[1] = c; }
    }
    __syncthreads();

    const float mu   = s_red[0] * (1.0f / DH);
    const float var  = s_red[1] * (1.0f / DH) - mu * mu;
    const float rstd = rsqrtf(var + LN_EPS);

    float4 g  = reinterpret_cast<const float4*>(gamma)[t];
    float4 be = reinterpret_cast<const float4*>(beta)[t];
    float4 h;
    h.x = fmaxf(0.f, (x.x - mu) * rstd * g.x + be.x);
    h.y = fmaxf(0.f, (x.y - mu) * rstd * g.y + be.y);
    h.z = fmaxf(0.f, (x.z - mu) * rstd * g.z + be.z);
    h.w = fmaxf(0.f, (x.w - mu) * rstd * g.w + be.w);
    reinterpret_cast<float4*>(s_h)[t] = h;
    __syncthreads();
}

// ---------------------------------------------------------------------------
// Kernel 2 (x2): h = relu(LN(base [+ yin])), then yout = A@h (warp-per-2-rows).
// grid = (16 chunks, 128 batches), 256 thr.
// ---------------------------------------------------------------------------
__global__ __launch_bounds__(256)
void matvec_ln_kernel(const float* __restrict__ A,
                      const float* __restrict__ yin,    // may be null
                      float* __restrict__ yout,
                      const float* __restrict__ gamma,
                      const float* __restrict__ beta)
{
    __shared__ float s_h[DH];
    __shared__ float s_red[16];

    const int b = blockIdx.y;
    const int chunk = blockIdx.x;
    const int t = threadIdx.x;
    const int w = t >> 5, lane = t & 31;

    compute_h(g_base + b * DH, yin ? yin + b * DH : nullptr,
              gamma, beta, s_h, s_red, t);

    const float4* __restrict__ Ab =
        reinterpret_cast<const float4*>(A + (size_t)b * DH * DH);
    const float4* h4 = reinterpret_cast<const float4*>(s_h);

    #pragma unroll
    for (int rr = 0; rr < 8; rr += 2) {
        const int r0 = chunk * 64 + w * 8 + rr;
        const float4* Ar0 = Ab + (size_t)r0 * 256;
        const float4* Ar1 = Ar0 + 256;

        float a00 = 0.f, a01 = 0.f, a10 = 0.f, a11 = 0.f;
        #pragma unroll
        for (int it = 0; it < 8; it += 2) {
            float4 v00 = __ldcs(Ar0 + lane + (it + 0) * 32);
            float4 v01 = __ldcs(Ar0 + lane + (it + 1) * 32);
            float4 v10 = __ldcs(Ar1 + lane + (it + 0) * 32);
            float4 v11 = __ldcs(Ar1 + lane + (it + 1) * 32);
            float4 h0  = h4[lane + (it + 0) * 32];
            float4 h1  = h4[lane + (it + 1) * 32];
            a00 += v00.x * h0.x + v00.y * h0.y + v00.z * h0.z + v00.w * h0.w;
            a01 += v01.x * h1.x + v01.y * h1.y + v01.z * h1.z + v01.w * h1.w;
            a10 += v10.x * h0.x + v10.y * h0.y + v10.z * h0.z + v10.w * h0.w;
            a11 += v11.x * h1.x + v11.y * h1.y + v11.z * h1.z + v11.w * h1.w;
        }
        float acc0 = a00 + a01;
        float acc1 = a10 + a11;
        #pragma unroll
        for (int o = 16; o > 0; o >>= 1) {
            acc0 += __shfl_xor_sync(0xffffffffu, acc0, o);
            acc1 += __shfl_xor_sync(0xffffffffu, acc1, o);
        }
        if (lane == 0) {
            yout[b * DH + r0]     = acc0;
            yout[b * DH + r0 + 1] = acc1;
        }
    }
}

// ---------------------------------------------------------------------------
// Kernel 3: fused (3rd matvec + update), persistent gangs.
// Gang = 64 blocks; block owns 16 rows; A tile read ONCE into smem, reused
// for the Hebbian update after a per-batch inter-block barrier.
// grid = 384 blocks (all co-resident: 256 thr, ~70KB smem -> 3 blocks/SM).
// ---------------------------------------------------------------------------
__global__ __launch_bounds__(256)
void fused_mv3_update_kernel(const float* __restrict__ A,
                             const float* __restrict__ yin,   // y1
                             const float* __restrict__ gamma,
                             const float* __restrict__ beta,
                             float* __restrict__ outH,
                             float* __restrict__ outA)
{
    extern __shared__ float sm[];
    float* tile  = sm;                       // 16 rows x 1024
    float* s_h   = sm + ROWS_PER_BLOCK * DH; // 1024
    float* s_red = s_h + DH;                 // 32

    const int gang = blockIdx.x / GANG_BLOCKS;
    const int cb   = blockIdx.x % GANG_BLOCKS;   // row-chunk within gang
    const int t    = threadIdx.x;
    const int w    = t >> 5, lane = t & 31;

    float4* tile4 = reinterpret_cast<float4*>(tile);
    const float4* h4 = reinterpret_cast<const float4*>(s_h);

    for (int b = gang; b < BATCH; b += GANGS) {
        // ---- h2 = relu(LN(base + y1)) ----
        compute_h(g_base + b * DH, yin + b * DH, gamma, beta, s_h, s_red, t);

        // ---- load A tile (16 rows) into smem; stream from HBM ----
        const float4* __restrict__ Ab =
            reinterpret_cast<const float4*>(A + (size_t)b * DH * DH) +
            (size_t)(cb * ROWS_PER_BLOCK) * 256;
        #pragma unroll
        for (int r = 0; r < ROWS_PER_BLOCK; r++)
            tile4[r * 256 + t] = __ldcs(Ab + r * 256 + t);
        __syncthreads();

        // ---- y2 rows: warp w handles local rows 2w, 2w+1 ----
        {
            const int r0 = 2 * w, r1 = 2 * w + 1;
            float a0 = 0.f, a1 = 0.f;
            #pragma unroll
            for (int i = 0; i < 8; i++) {
                float4 hv = h4[lane + i * 32];
                float4 v0 = tile4[r0 * 256 + lane + i * 32];
                float4 v1 = tile4[r1 * 256 + lane + i * 32];
                a0 += v0.x * hv.x + v0.y * hv.y + v0.z * hv.z + v0.w * hv.w;
                a1 += v1.x * hv.x + v1.y * hv.y + v1.z * hv.z + v1.w * hv.w;
            }
            #pragma unroll
            for (int o = 16; o > 0; o >>= 1) {
                a0 += __shfl_xor_sync(0xffffffffu, a0, o);
                a1 += __shfl_xor_sync(0xffffffffu, a1, o);
            }
            if (lane == 0) {
                g_y0[b * DH + cb * ROWS_PER_BLOCK + r0] = a0;
                g_y0[b * DH + cb * ROWS_PER_BLOCK + r1] = a1;
            }
        }
        __threadfence();
        __syncthreads();

        // ---- gang barrier on this batch ----
        if (t == 0) {
            atomicAdd(&g_arrive[b], 1);
            while (atomicAdd(&g_arrive[b], 0) < GANG_BLOCKS)
                __nanosleep(64);
            __threadfence();
        }
        __syncthreads();

        // ---- h3 = relu(LN(base + y2)) ----
        compute_h(g_base + b * DH, g_y0 + b * DH, gamma, beta, s_h, s_red, t);

        if (cb == 0)
            reinterpret_cast<float4*>(outH + b * DH)[t] = h4[t];

        // ---- A_k rows from the smem tile (no second HBM read) ----
        float4* __restrict__ Ob =
            reinterpret_cast<float4*>(outA + (size_t)b * DH * DH) +
            (size_t)(cb * ROWS_PER_BLOCK) * 256;
        const float4 hv = h4[t];
        #pragma unroll
        for (int r = 0; r < ROWS_PER_BLOCK; r++) {
            const float hi = s_h[cb * ROWS_PER_BLOCK + r] * ETA;
            float4 a = tile4[r * 256 + t];
            float4 o;
            o.x = fmaf(LAM, a.x, hi * hv.x);
            o.y = fmaf(LAM, a.y, hi * hv.y);
            o.z = fmaf(LAM, a.z, hi * hv.z);
            o.w = fmaf(LAM, a.w, hi * hv.w);
            __stcs(Ob + r * 256 + t, o);
        }
        __syncthreads();   // protect tile/s_h before next batch
    }
}

// ---------------------------------------------------------------------------
extern "C" void kernel_launch(void* const* d_in, const int* in_sizes, int n_in,
                              void* d_out, int out_size)
{
    const float* z      = (const float*)d_in[0];
    const float* h_prev = (const float*)d_in[1];
    const float* A_prev = (const float*)d_in[2];
    const float* W_h    = (const float*)d_in[3];
    const float* W_g    = (const float*)d_in[4];
    const float* b_h    = (const float*)d_in[5];
    const float* gamma  = (const float*)d_in[6];
    const float* beta   = (const float*)d_in[7];

    float* outH = (float*)d_out;                 // h_t: 128*1024
    float* outA = (float*)d_out + BATCH * DH;    // A_k: 128*1024*1024

    float* y0;  cudaGetSymbolAddress((void**)&y0, g_y0);
    float* y1;  cudaGetSymbolAddress((void**)&y1, g_y1);

    cudaFuncSetAttribute(fused_mv3_update_kernel,
                         cudaFuncAttributeMaxDynamicSharedMemorySize,
                         (int)FUSED_SMEM);

    base_gemm_kernel<<<dim3(BATCH / 32, DH / 32), 256>>>(h_prev, z, W_h, W_g, b_h);

    matvec_ln_kernel<<<dim3(16, BATCH), 256>>>(A_prev, nullptr, y0, gamma, beta);
    matvec_ln_kernel<<<dim3(16, BATCH), 256>>>(A_prev, y0,      y1, gamma, beta);

    fused_mv3_update_kernel<<<FUSED_GRID, 256, FUSED_SMEM>>>(
        A_prev, y1, gamma, beta, outH, outA);
}